// round 6
// baseline (speedup 1.0000x reference)
#include <cuda_runtime.h>

#define NN   100000
#define NE   1600000
#define FIN  128
#define D    64
#define NCENT 100
#define NCLS  10
#define EPSV 1e-12f

// ---------------- device scratch (no allocation allowed) ----------------
__device__ float g_h[NN * D];
__device__ float g_hw[NN * D];
__device__ float g_dinv[NN];
__device__ int   g_deg[NN];
__device__ int   g_rs[NN + 1];
__device__ int   g_cursor[NN];
__device__ int   g_csr[NE];
__device__ int   g_bsum[128];
__device__ int   g_boff[128];
__device__ float g_M[D * FIN];
__device__ float g_pooled[NCENT];
__device__ int   g_is64;

// ---------------- dtype detection: int64 edge_index has zero hi-words ----
__global__ void k_detect(const int* __restrict__ w) {
    if (threadIdx.x == 0 && blockIdx.x == 0) {
        int nz = 0;
        for (int i = 0; i < 64; i++) nz += (w[2 * i + 1] != 0);
        g_is64 = (nz == 0) ? 1 : 0;
    }
}

// ---------------- small utility kernels ----------------
__global__ void k_zero_deg() {
    int i = blockIdx.x * blockDim.x + threadIdx.x;
    if (i < NN) g_deg[i] = 0;
}

__global__ void k_zero_pooled() {
    int i = threadIdx.x;
    if (i < NCENT) g_pooled[i] = 0.f;
}

__device__ __forceinline__ int load_idx(const int* w, long long pos) {
    // pos-th logical element of edge_index flat array (row-major [2, NE])
    return g_is64 ? w[2 * pos] : w[pos];   // little-endian low word == value
}

__global__ void k_degree(const int* __restrict__ w) {
    int e = blockIdx.x * blockDim.x + threadIdx.x;
    if (e < NE) {
        int dst = load_idx(w, (long long)NE + e);
        if ((unsigned)dst < NN) atomicAdd(&g_deg[dst], 1);
    }
}

__global__ void k_dinv() {
    int i = blockIdx.x * blockDim.x + threadIdx.x;
    if (i < NN) {
        float d = (float)(g_deg[i] + 1);   // +1 self loop; always >= 1
        g_dinv[i] = rsqrtf(d);
    }
}

// ---------------- exclusive scan of g_deg -> g_rs ----------------
__global__ void k_scan1() {
    __shared__ int s[1024];
    int t = threadIdx.x;
    int gid = blockIdx.x * 1024 + t;
    int v = (gid < NN) ? g_deg[gid] : 0;
    s[t] = v;
    __syncthreads();
    for (int off = 1; off < 1024; off <<= 1) {
        int x = (t >= off) ? s[t - off] : 0;
        __syncthreads();
        s[t] += x;
        __syncthreads();
    }
    if (gid < NN) g_rs[gid] = s[t] - v;    // exclusive
    if (t == 1023) g_bsum[blockIdx.x] = s[1023];
}

__global__ void k_scan2(int nblk) {
    if (threadIdx.x == 0 && blockIdx.x == 0) {
        int run = 0;
        for (int b = 0; b < nblk; b++) {
            g_boff[b] = run;
            run += g_bsum[b];
        }
    }
}

__global__ void k_scan3() {
    int t = threadIdx.x;
    int gid = blockIdx.x * 1024 + t;
    if (gid < NN) {
        int v = g_rs[gid] + g_boff[blockIdx.x];
        g_rs[gid] = v;
        g_cursor[gid] = v;
    }
    if (gid == 0) g_rs[NN] = 0;   // unused sentinel; real end set below
}

__global__ void k_set_end() {
    if (threadIdx.x == 0) {
        // total edge count actually binned (== NE when all indices valid)
        g_rs[NN] = g_rs[NN - 1] + g_deg[NN - 1];
    }
}

__global__ void k_fill_csr(const int* __restrict__ w) {
    int e = blockIdx.x * blockDim.x + threadIdx.x;
    if (e < NE) {
        int src = load_idx(w, e);
        int dst = load_idx(w, (long long)NE + e);
        if ((unsigned)dst < NN && (unsigned)src < NN) {
            int p = atomicAdd(&g_cursor[dst], 1);
            g_csr[p] = src;
        }
    }
}

// ---------------- fused weight: M = W_gcn[0] @ W_embed   [64 x 128] ----------------
__global__ void k_computeM(const float* __restrict__ W0, const float* __restrict__ We) {
    int idx = blockIdx.x * blockDim.x + threadIdx.x;
    if (idx < D * FIN) {
        int r = idx / FIN, c = idx % FIN;
        float s = 0.f;
        #pragma unroll
        for (int k = 0; k < D; k++) s += W0[r * D + k] * We[k * FIN + c];
        g_M[idx] = s;
    }
}

// ---------------- register/shared tiled GEMM body ----------------
// out[n][c] = sum_k A[n][k] * W[c][k];  64x64 block tile, 256 thr, 4x4 accum.
template <int KTOT>
__device__ __forceinline__ void gemm_body(const float* __restrict__ A,
                                          const float* __restrict__ W,
                                          float* __restrict__ out) {
    __shared__ float sA[64][65];
    __shared__ float sW[64][65];
    int t = threadIdx.x;
    int tn = t >> 4;       // 0..15 node group
    int tc = t & 15;       // 0..15 col group
    int nodeBase = blockIdx.x * 64;

    float acc[4][4];
    #pragma unroll
    for (int i = 0; i < 4; i++)
        #pragma unroll
        for (int j = 0; j < 4; j++) acc[i][j] = 0.f;

    for (int k0 = 0; k0 < KTOT; k0 += 64) {
        for (int i = t; i < 4096; i += 256) {
            int n = i >> 6, k = i & 63;
            int gn = nodeBase + n;
            sA[n][k] = (gn < NN) ? A[(long long)gn * KTOT + k0 + k] : 0.f;
        }
        for (int i = t; i < 4096; i += 256) {
            int c = i >> 6, k = i & 63;
            sW[c][k] = W[c * KTOT + k0 + k];
        }
        __syncthreads();
        #pragma unroll 8
        for (int k = 0; k < 64; k++) {
            float a0 = sA[tn * 4 + 0][k];
            float a1 = sA[tn * 4 + 1][k];
            float a2 = sA[tn * 4 + 2][k];
            float a3 = sA[tn * 4 + 3][k];
            float b0 = sW[tc * 4 + 0][k];
            float b1 = sW[tc * 4 + 1][k];
            float b2 = sW[tc * 4 + 2][k];
            float b3 = sW[tc * 4 + 3][k];
            acc[0][0] += a0 * b0; acc[0][1] += a0 * b1; acc[0][2] += a0 * b2; acc[0][3] += a0 * b3;
            acc[1][0] += a1 * b0; acc[1][1] += a1 * b1; acc[1][2] += a1 * b2; acc[1][3] += a1 * b3;
            acc[2][0] += a2 * b0; acc[2][1] += a2 * b1; acc[2][2] += a2 * b2; acc[2][3] += a2 * b3;
            acc[3][0] += a3 * b0; acc[3][1] += a3 * b1; acc[3][2] += a3 * b2; acc[3][3] += a3 * b3;
        }
        __syncthreads();
    }
    #pragma unroll
    for (int i = 0; i < 4; i++) {
        int gn = nodeBase + tn * 4 + i;
        if (gn < NN) {
            float4 v = make_float4(acc[i][0], acc[i][1], acc[i][2], acc[i][3]);
            *reinterpret_cast<float4*>(&out[(long long)gn * D + tc * 4]) = v;
        }
    }
}

// layer 0: A = x (harness ptr), W = g_M, out = g_hw
__global__ __launch_bounds__(256) void k_gemm0(const float* __restrict__ x) {
    gemm_body<FIN>(x, g_M, g_hw);
}
// layers 1-2: A = g_h, W = harness ptr, out = g_hw
__global__ __launch_bounds__(256) void k_gemm12(const float* __restrict__ W) {
    gemm_body<D>(g_h, W, g_hw);
}

// ---------------- CSR aggregation + self-loop + bias + relu ----------------
// one warp per node; lane handles features (lane, lane+32)
__global__ __launch_bounds__(256) void k_aggregate(const float* __restrict__ bias) {
    int warp = (blockIdx.x * blockDim.x + threadIdx.x) >> 5;
    int lane = threadIdx.x & 31;
    if (warp >= NN) return;
    int i = warp;
    int s0 = g_rs[i];
    int s1 = g_rs[i] + g_deg[i];
    float acc0 = 0.f, acc1 = 0.f;
    for (int e = s0; e < s1; e++) {
        int s = g_csr[e];
        float wgt = g_dinv[s];
        acc0 += wgt * g_hw[(long long)s * D + lane];
        acc1 += wgt * g_hw[(long long)s * D + 32 + lane];
    }
    float di = g_dinv[i];
    float self = di * di;
    float v0 = di * acc0 + self * g_hw[(long long)i * D + lane]      + bias[lane];
    float v1 = di * acc1 + self * g_hw[(long long)i * D + 32 + lane] + bias[32 + lane];
    g_h[(long long)i * D + lane]      = fmaxf(v0, 0.f);
    g_h[(long long)i * D + 32 + lane] = fmaxf(v1, 0.f);
}

// ---------------- fused centroid distance + mean pooling ----------------
__global__ __launch_bounds__(256) void k_distpool(const float* __restrict__ cent) {
    __shared__ float sC[NCENT * D];
    __shared__ float sc2[NCENT];
    __shared__ float sPool[NCENT];
    int t = threadIdx.x;
    for (int i = t; i < NCENT * D; i += 256) sC[i] = cent[i];
    if (t < NCENT) sPool[t] = 0.f;
    __syncthreads();
    if (t < NCENT) {
        float s = 0.f;
        #pragma unroll
        for (int j = 0; j < D; j++) s += sC[t * D + j] * sC[t * D + j];
        sc2[t] = s;
    }
    __syncthreads();

    int i = blockIdx.x * 256 + t;
    bool valid = (i < NN);
    float hreg[D];
    float h2 = 0.f;
    if (valid) {
        #pragma unroll
        for (int j = 0; j < D; j++) {
            float v = g_h[(long long)i * D + j];
            hreg[j] = v;
            h2 += v * v;
        }
    } else {
        #pragma unroll
        for (int j = 0; j < D; j++) hreg[j] = 0.f;
    }

    int lane = t & 31;
    for (int k = 0; k < NCENT; k++) {
        float dot = 0.f;
        #pragma unroll
        for (int j = 0; j < D; j++) dot += hreg[j] * sC[k * D + j];
        float d2 = fmaxf(h2 + sc2[k] - 2.f * dot, 0.f);
        float dist = valid ? sqrtf(d2 + EPSV) : 0.f;
        #pragma unroll
        for (int off = 16; off > 0; off >>= 1)
            dist += __shfl_down_sync(0xFFFFFFFFu, dist, off);
        if (lane == 0) atomicAdd(&sPool[k], dist);
    }
    __syncthreads();
    if (t < NCENT) atomicAdd(&g_pooled[t], sPool[t]);
}

// ---------------- final linear head ----------------
__global__ void k_out(const float* __restrict__ Wout, const float* __restrict__ bout,
                      float* __restrict__ out) {
    int c = threadIdx.x;
    if (c < NCLS) {
        const float invN = 1.0f / (float)NN;
        float s = 0.f;
        #pragma unroll
        for (int k = 0; k < NCENT; k++) s += (g_pooled[k] * invN) * Wout[c * NCENT + k];
        out[c] = s + bout[c];
    }
}

// ---------------- launch ----------------
extern "C" void kernel_launch(void* const* d_in, const int* in_sizes, int n_in,
                              void* d_out, int out_size) {
    const float* x    = (const float*)d_in[0];
    const int*   eiw  = (const int*)d_in[1];     // raw words; dtype detected on device
    const float* We   = (const float*)d_in[2];
    const float* Wg   = (const float*)d_in[3];   // [3,64,64]
    const float* bg   = (const float*)d_in[4];   // [3,64]
    const float* cent = (const float*)d_in[5];   // [100,64]
    const float* Wout = (const float*)d_in[6];   // [10,100]
    const float* bout = (const float*)d_in[7];   // [10]
    float*       out  = (float*)d_out;

    const int nScanBlk = (NN + 1023) / 1024;           // 98
    const int edgeBlk  = (NE + 255) / 256;             // 6250
    const int nodeBlk  = (NN + 255) / 256;             // 391
    const int gemmBlk  = (NN + 63) / 64;               // 1563
    const int aggBlk   = (NN * 32 + 255) / 256;        // 12500

    // dtype detect + CSR/norm build
    k_detect<<<1, 32>>>(eiw);
    k_zero_deg<<<nodeBlk, 256>>>();
    k_zero_pooled<<<1, 128>>>();
    k_degree<<<edgeBlk, 256>>>(eiw);
    k_dinv<<<nodeBlk, 256>>>();
    k_scan1<<<nScanBlk, 1024>>>();
    k_scan2<<<1, 32>>>(nScanBlk);
    k_scan3<<<nScanBlk, 1024>>>();
    k_set_end<<<1, 32>>>();
    k_fill_csr<<<edgeBlk, 256>>>(eiw);

    // fused embed + layer0 weight:  M = W_gcn[0] @ W_embed
    k_computeM<<<(D * FIN + 255) / 256, 256>>>(Wg, We);

    // layer 0 (fused): hw = x @ M^T
    k_gemm0<<<gemmBlk, 256>>>(x);
    k_aggregate<<<aggBlk, 256>>>(bg + 0 * D);

    // layer 1
    k_gemm12<<<gemmBlk, 256>>>(Wg + 1 * D * D);
    k_aggregate<<<aggBlk, 256>>>(bg + 1 * D);

    // layer 2
    k_gemm12<<<gemmBlk, 256>>>(Wg + 2 * D * D);
    k_aggregate<<<aggBlk, 256>>>(bg + 2 * D);

    // distance + pooling + head
    k_distpool<<<nodeBlk, 256>>>(cent);
    k_out<<<1, 32>>>(Wout, bout, out);
}

// round 8
// speedup vs baseline: 1.1573x; 1.1573x over previous
#include <cuda_runtime.h>
#include <cstdint>

#define NN   100000
#define NE   1600000
#define FIN  128
#define D    64
#define NCENT 100
#define NCLS  10
#define EPSV 1e-12f

// ---------------- device scratch (no allocation allowed) ----------------
__device__ float g_h[NN * D];
__device__ float g_hw[NN * D];
__device__ float g_dinv[NN];
__device__ int   g_deg[NN];
__device__ int   g_rs[NN + 1];
__device__ int   g_cursor[NN];
__device__ int   g_csr[NE];
__device__ int   g_bsum[128];
__device__ int   g_boff[128];
__device__ float g_M[D * FIN];
__device__ float g_pooled[NCENT];
__device__ int   g_is64;

// ---------------- init: zero deg/pooled + dtype detect ----------------
__global__ void k_init(const int* __restrict__ w) {
    int i = blockIdx.x * blockDim.x + threadIdx.x;
    if (i < NN) g_deg[i] = 0;
    if (i < NCENT) g_pooled[i] = 0.f;
    if (i == 0) {
        int nz = 0;
        for (int j = 0; j < 64; j++) nz += (w[2 * j + 1] != 0);
        g_is64 = (nz == 0) ? 1 : 0;
    }
}

__device__ __forceinline__ int load_idx(const int* w, long long pos) {
    return g_is64 ? w[2 * pos] : w[pos];   // little-endian low word == value
}

__global__ void k_degree(const int* __restrict__ w) {
    int e = blockIdx.x * blockDim.x + threadIdx.x;
    if (e < NE) {
        int dst = load_idx(w, (long long)NE + e);
        if ((unsigned)dst < NN) atomicAdd(&g_deg[dst], 1);
    }
}

// ---------------- exclusive scan of g_deg -> g_rs (+ dinv fused) ----------
__global__ void k_scan1() {
    __shared__ int s[1024];
    int t = threadIdx.x;
    int gid = blockIdx.x * 1024 + t;
    int v = (gid < NN) ? g_deg[gid] : 0;
    if (gid < NN) g_dinv[gid] = rsqrtf((float)(v + 1));   // fused: +1 self loop
    s[t] = v;
    __syncthreads();
    for (int off = 1; off < 1024; off <<= 1) {
        int x = (t >= off) ? s[t - off] : 0;
        __syncthreads();
        s[t] += x;
        __syncthreads();
    }
    if (gid < NN) g_rs[gid] = s[t] - v;    // exclusive
    if (t == 1023) g_bsum[blockIdx.x] = s[1023];
}

__global__ void k_scan2(int nblk) {
    if (threadIdx.x == 0 && blockIdx.x == 0) {
        int run = 0;
        for (int b = 0; b < nblk; b++) {
            g_boff[b] = run;
            run += g_bsum[b];
        }
    }
}

__global__ void k_scan3() {
    int t = threadIdx.x;
    int gid = blockIdx.x * 1024 + t;
    if (gid < NN) {
        int v = g_rs[gid] + g_boff[blockIdx.x];
        g_rs[gid] = v;
        g_cursor[gid] = v;
    }
}

__global__ void k_fill_csr(const int* __restrict__ w) {
    int e = blockIdx.x * blockDim.x + threadIdx.x;
    if (e < NE) {
        int src = load_idx(w, e);
        int dst = load_idx(w, (long long)NE + e);
        if ((unsigned)dst < NN && (unsigned)src < NN) {
            int p = atomicAdd(&g_cursor[dst], 1);
            g_csr[p] = src;
        }
    }
}

// ---------------- fused weight: M = W_gcn[0] @ W_embed   [64 x 128] -----
__global__ void k_computeM(const float* __restrict__ W0, const float* __restrict__ We) {
    int idx = blockIdx.x * blockDim.x + threadIdx.x;
    if (idx < D * FIN) {
        int r = idx / FIN, c = idx % FIN;
        float s = 0.f;
        #pragma unroll
        for (int k = 0; k < D; k++) s += W0[r * D + k] * We[k * FIN + c];
        g_M[idx] = s;
    }
}

// ---------------- tf32 tensor-core GEMM: out[n][c] = sum_k A[n][k]*W[c][k]
// block = 128 thr (4 warps); block tile 64 rows x 64 cols; warp = 16 rows.
// mma.sync.m16n8k8 tf32, fp32 accumulate. K consumed in 64-wide chunks.
template <int KTOT>
__device__ __forceinline__ void gemm_tc_body(const float* __restrict__ A,
                                             const float* __restrict__ W,
                                             float* __restrict__ out) {
    __shared__ uint32_t sA[64][68];
    __shared__ uint32_t sW[64][68];
    int t = threadIdx.x;
    int warp = t >> 5, lane = t & 31;
    int grp = lane >> 2, tig = lane & 3;     // groupID / threadID-in-group
    int rowBase = blockIdx.x * 64 + warp * 16;

    float c[8][4];
    #pragma unroll
    for (int nt = 0; nt < 8; nt++)
        #pragma unroll
        for (int j = 0; j < 4; j++) c[nt][j] = 0.f;

    for (int kc = 0; kc < KTOT; kc += 64) {
        for (int i = t; i < 4096; i += 128) {
            int r = i >> 6, k = i & 63;
            int gn = blockIdx.x * 64 + r;
            float av = (gn < NN) ? A[(long long)gn * KTOT + kc + k] : 0.f;
            float wv = W[r * KTOT + kc + k];
            uint32_t ai, wi;
            asm("cvt.rna.tf32.f32 %0, %1;" : "=r"(ai) : "f"(av));
            asm("cvt.rna.tf32.f32 %0, %1;" : "=r"(wi) : "f"(wv));
            sA[r][k] = ai;
            sW[r][k] = wi;
        }
        __syncthreads();
        #pragma unroll
        for (int k0 = 0; k0 < 64; k0 += 8) {
            uint32_t a0 = sA[warp * 16 + grp][k0 + tig];
            uint32_t a1 = sA[warp * 16 + grp + 8][k0 + tig];
            uint32_t a2 = sA[warp * 16 + grp][k0 + tig + 4];
            uint32_t a3 = sA[warp * 16 + grp + 8][k0 + tig + 4];
            #pragma unroll
            for (int nt = 0; nt < 8; nt++) {
                uint32_t b0 = sW[nt * 8 + grp][k0 + tig];
                uint32_t b1 = sW[nt * 8 + grp][k0 + tig + 4];
                asm volatile(
                    "mma.sync.aligned.m16n8k8.row.col.f32.tf32.tf32.f32 "
                    "{%0,%1,%2,%3}, {%4,%5,%6,%7}, {%8,%9}, {%0,%1,%2,%3};"
                    : "+f"(c[nt][0]), "+f"(c[nt][1]), "+f"(c[nt][2]), "+f"(c[nt][3])
                    : "r"(a0), "r"(a1), "r"(a2), "r"(a3), "r"(b0), "r"(b1));
            }
        }
        __syncthreads();
    }
    int r0 = rowBase + grp;
    int r1 = rowBase + grp + 8;
    #pragma unroll
    for (int nt = 0; nt < 8; nt++) {
        int col = nt * 8 + tig * 2;
        if (r0 < NN)
            *reinterpret_cast<float2*>(&out[(long long)r0 * D + col]) = make_float2(c[nt][0], c[nt][1]);
        if (r1 < NN)
            *reinterpret_cast<float2*>(&out[(long long)r1 * D + col]) = make_float2(c[nt][2], c[nt][3]);
    }
}

__global__ __launch_bounds__(128) void k_gemm0_tc(const float* __restrict__ x) {
    gemm_tc_body<FIN>(x, g_M, g_hw);
}
__global__ __launch_bounds__(128) void k_gemm12_tc(const float* __restrict__ W) {
    gemm_tc_body<D>(g_h, W, g_hw);
}

// ---------------- CSR aggregation + self-loop + bias + relu -------------
// one warp per node; lane handles feature pair (2*lane, 2*lane+1) via float2.
// unroll-by-4 with batched index loads to raise MLP.
__global__ __launch_bounds__(256) void k_aggregate(const float* __restrict__ bias) {
    int warp = (blockIdx.x * blockDim.x + threadIdx.x) >> 5;
    int lane = threadIdx.x & 31;
    if (warp >= NN) return;
    int i = warp;
    int s0 = g_rs[i];
    int deg = g_deg[i];
    const float2* hw2 = reinterpret_cast<const float2*>(g_hw);
    float accx = 0.f, accy = 0.f;
    int e = s0, end = s0 + deg;
    for (; e + 4 <= end; e += 4) {
        int sa = g_csr[e], sb = g_csr[e + 1], sc = g_csr[e + 2], sd = g_csr[e + 3];
        float wa = g_dinv[sa], wb = g_dinv[sb], wc = g_dinv[sc], wd = g_dinv[sd];
        float2 va = __ldg(&hw2[sa * 32 + lane]);
        float2 vb = __ldg(&hw2[sb * 32 + lane]);
        float2 vc = __ldg(&hw2[sc * 32 + lane]);
        float2 vd = __ldg(&hw2[sd * 32 + lane]);
        accx += wa * va.x + wb * vb.x + wc * vc.x + wd * vd.x;
        accy += wa * va.y + wb * vb.y + wc * vc.y + wd * vd.y;
    }
    for (; e < end; e++) {
        int s = g_csr[e];
        float w = g_dinv[s];
        float2 v = __ldg(&hw2[s * 32 + lane]);
        accx += w * v.x;
        accy += w * v.y;
    }
    float di = g_dinv[i];
    float self = di * di;
    float2 hv = hw2[i * 32 + lane];
    float2 bb = reinterpret_cast<const float2*>(bias)[lane];
    float vx = di * accx + self * hv.x + bb.x;
    float vy = di * accy + self * hv.y + bb.y;
    reinterpret_cast<float2*>(g_h)[i * 32 + lane] = make_float2(fmaxf(vx, 0.f), fmaxf(vy, 0.f));
}

// ---------------- fused centroid distance + mean pooling ----------------
__global__ __launch_bounds__(256) void k_distpool(const float* __restrict__ cent) {
    __shared__ float sC[NCENT * D];
    __shared__ float sc2[NCENT];
    __shared__ float sPool[NCENT];
    int t = threadIdx.x;
    for (int i = t; i < NCENT * D; i += 256) sC[i] = cent[i];
    if (t < NCENT) sPool[t] = 0.f;
    __syncthreads();
    if (t < NCENT) {
        float s = 0.f;
        #pragma unroll
        for (int j = 0; j < D; j++) s += sC[t * D + j] * sC[t * D + j];
        sc2[t] = s;
    }
    __syncthreads();

    int i = blockIdx.x * 256 + t;
    bool valid = (i < NN);
    float hreg[D];
    float h2 = 0.f;
    if (valid) {
        #pragma unroll
        for (int j = 0; j < D; j++) {
            float v = g_h[(long long)i * D + j];
            hreg[j] = v;
            h2 += v * v;
        }
    } else {
        #pragma unroll
        for (int j = 0; j < D; j++) hreg[j] = 0.f;
    }

    int lane = t & 31;
    for (int k = 0; k < NCENT; k++) {
        float dot = 0.f;
        #pragma unroll
        for (int j = 0; j < D; j++) dot += hreg[j] * sC[k * D + j];
        float d2 = fmaxf(h2 + sc2[k] - 2.f * dot, 0.f);
        float dist = valid ? sqrtf(d2 + EPSV) : 0.f;
        #pragma unroll
        for (int off = 16; off > 0; off >>= 1)
            dist += __shfl_down_sync(0xFFFFFFFFu, dist, off);
        if (lane == 0) atomicAdd(&sPool[k], dist);
    }
    __syncthreads();
    if (t < NCENT) atomicAdd(&g_pooled[t], sPool[t]);
}

// ---------------- final linear head ----------------
__global__ void k_out(const float* __restrict__ Wout, const float* __restrict__ bout,
                      float* __restrict__ out) {
    int c = threadIdx.x;
    if (c < NCLS) {
        const float invN = 1.0f / (float)NN;
        float s = 0.f;
        #pragma unroll
        for (int k = 0; k < NCENT; k++) s += (g_pooled[k] * invN) * Wout[c * NCENT + k];
        out[c] = s + bout[c];
    }
}

// ---------------- launch ----------------
extern "C" void kernel_launch(void* const* d_in, const int* in_sizes, int n_in,
                              void* d_out, int out_size) {
    const float* x    = (const float*)d_in[0];
    const int*   eiw  = (const int*)d_in[1];     // raw words; dtype detected on device
    const float* We   = (const float*)d_in[2];
    const float* Wg   = (const float*)d_in[3];   // [3,64,64]
    const float* bg   = (const float*)d_in[4];   // [3,64]
    const float* cent = (const float*)d_in[5];   // [100,64]
    const float* Wout = (const float*)d_in[6];   // [10,100]
    const float* bout = (const float*)d_in[7];   // [10]
    float*       out  = (float*)d_out;

    const int nScanBlk = (NN + 1023) / 1024;           // 98
    const int edgeBlk  = (NE + 255) / 256;             // 6250
    const int nodeBlk  = (NN + 255) / 256;             // 391
    const int gemmBlk  = (NN + 63) / 64;               // 1563
    const int aggBlk   = (NN * 32 + 255) / 256;        // 12500

    // init + CSR/norm build
    k_init<<<nodeBlk, 256>>>(eiw);
    k_degree<<<edgeBlk, 256>>>(eiw);
    k_scan1<<<nScanBlk, 1024>>>();
    k_scan2<<<1, 32>>>(nScanBlk);
    k_scan3<<<nScanBlk, 1024>>>();
    k_fill_csr<<<edgeBlk, 256>>>(eiw);

    // fused embed + layer0 weight:  M = W_gcn[0] @ W_embed
    k_computeM<<<(D * FIN + 255) / 256, 256>>>(Wg, We);

    // layer 0 (fused): hw = x @ M^T   (tf32 tensor cores)
    k_gemm0_tc<<<gemmBlk, 128>>>(x);
    k_aggregate<<<aggBlk, 256>>>(bg + 0 * D);

    // layer 1
    k_gemm12_tc<<<gemmBlk, 128>>>(Wg + 1 * D * D);
    k_aggregate<<<aggBlk, 256>>>(bg + 1 * D);

    // layer 2
    k_gemm12_tc<<<gemmBlk, 128>>>(Wg + 2 * D * D);
    k_aggregate<<<aggBlk, 256>>>(bg + 2 * D);

    // distance + pooling + head
    k_distpool<<<nodeBlk, 256>>>(cent);
    k_out<<<1, 32>>>(Wout, bout, out);
}

// round 10
// speedup vs baseline: 1.3642x; 1.1788x over previous
#include <cuda_runtime.h>
#include <cuda_bf16.h>
#include <cstdint>

#define NN   100000
#define NE   1600000
#define FIN  128
#define D    64
#define NCENT 100
#define NPAD  104
#define NCLS  10
#define EPSV 1e-12f

// ---------------- device scratch (no allocation allowed) ----------------
__device__ float           g_h[NN * D];          // fp32 post-aggregation activations
__device__ __nv_bfloat162  g_hwb[NN * D / 2];    // bf16 prescaled hw: dinv[n]*hw[n][:]
__device__ float g_dinv[NN];
__device__ int   g_deg[NN];
__device__ int   g_rs[NN + 1];
__device__ int   g_cursor[NN];
__device__ int   g_csr[NE];
__device__ int   g_bsum[128];
__device__ int   g_boff[128];
__device__ float g_M[D * FIN];
__device__ float g_pooled[NCENT];
__device__ int   g_is64;

// ---------------- init: zero deg/pooled + dtype detect ----------------
__global__ void k_init(const int* __restrict__ w) {
    int i = blockIdx.x * blockDim.x + threadIdx.x;
    if (i < NN) g_deg[i] = 0;
    if (i < NCENT) g_pooled[i] = 0.f;
    if (i == 0) {
        int nz = 0;
        for (int j = 0; j < 64; j++) nz += (w[2 * j + 1] != 0);
        g_is64 = (nz == 0) ? 1 : 0;
    }
}

__device__ __forceinline__ int load_idx(const int* w, long long pos) {
    return g_is64 ? w[2 * pos] : w[pos];   // little-endian low word == value
}

__global__ void k_degree(const int* __restrict__ w) {
    int e = blockIdx.x * blockDim.x + threadIdx.x;
    if (e < NE) {
        int dst = load_idx(w, (long long)NE + e);
        if ((unsigned)dst < NN) atomicAdd(&g_deg[dst], 1);
    }
}

// ---------------- exclusive scan of g_deg -> g_rs (+ dinv fused) ----------
__global__ void k_scan1() {
    __shared__ int s[1024];
    int t = threadIdx.x;
    int gid = blockIdx.x * 1024 + t;
    int v = (gid < NN) ? g_deg[gid] : 0;
    if (gid < NN) g_dinv[gid] = rsqrtf((float)(v + 1));   // fused: +1 self loop
    s[t] = v;
    __syncthreads();
    for (int off = 1; off < 1024; off <<= 1) {
        int x = (t >= off) ? s[t - off] : 0;
        __syncthreads();
        s[t] += x;
        __syncthreads();
    }
    if (gid < NN) g_rs[gid] = s[t] - v;    // exclusive
    if (t == 1023) g_bsum[blockIdx.x] = s[1023];
}

// parallel scan over block sums (nblk <= 128)
__global__ void k_scan2(int nblk) {
    __shared__ int s[128];
    int t = threadIdx.x;
    int v = (t < nblk) ? g_bsum[t] : 0;
    s[t] = v;
    __syncthreads();
    for (int off = 1; off < 128; off <<= 1) {
        int x = (t >= off) ? s[t - off] : 0;
        __syncthreads();
        s[t] += x;
        __syncthreads();
    }
    if (t < nblk) g_boff[t] = s[t] - v;    // exclusive
}

__global__ void k_scan3() {
    int t = threadIdx.x;
    int gid = blockIdx.x * 1024 + t;
    if (gid < NN) {
        int v = g_rs[gid] + g_boff[blockIdx.x];
        g_rs[gid] = v;
        g_cursor[gid] = v;
    }
}

__global__ void k_fill_csr(const int* __restrict__ w) {
    int e = blockIdx.x * blockDim.x + threadIdx.x;
    if (e < NE) {
        int src = load_idx(w, e);
        int dst = load_idx(w, (long long)NE + e);
        if ((unsigned)dst < NN && (unsigned)src < NN) {
            int p = atomicAdd(&g_cursor[dst], 1);
            g_csr[p] = src;
        }
    }
}

// ---------------- fused weight: M = W_gcn[0] @ W_embed   [64 x 128] -----
__global__ void k_computeM(const float* __restrict__ W0, const float* __restrict__ We) {
    int idx = blockIdx.x * blockDim.x + threadIdx.x;
    if (idx < D * FIN) {
        int r = idx / FIN, c = idx % FIN;
        float s = 0.f;
        #pragma unroll
        for (int k = 0; k < D; k++) s += W0[r * D + k] * We[k * FIN + c];
        g_M[idx] = s;
    }
}

// ---------------- tf32 tensor-core GEMM, epilogue: prescale by dinv, store bf16
// out_bf16[n][c] = dinv[n] * sum_k A[n][k]*W[c][k]
template <int KTOT>
__device__ __forceinline__ void gemm_tc_body(const float* __restrict__ A,
                                             const float* __restrict__ W) {
    __shared__ uint32_t sA[64][68];
    __shared__ uint32_t sW[64][68];
    int t = threadIdx.x;
    int warp = t >> 5, lane = t & 31;
    int grp = lane >> 2, tig = lane & 3;
    int rowBase = blockIdx.x * 64 + warp * 16;

    float c[8][4];
    #pragma unroll
    for (int nt = 0; nt < 8; nt++)
        #pragma unroll
        for (int j = 0; j < 4; j++) c[nt][j] = 0.f;

    for (int kc = 0; kc < KTOT; kc += 64) {
        for (int i = t; i < 4096; i += 128) {
            int r = i >> 6, k = i & 63;
            int gn = blockIdx.x * 64 + r;
            float av = (gn < NN) ? A[(long long)gn * KTOT + kc + k] : 0.f;
            float wv = W[r * KTOT + kc + k];
            uint32_t ai, wi;
            asm("cvt.rna.tf32.f32 %0, %1;" : "=r"(ai) : "f"(av));
            asm("cvt.rna.tf32.f32 %0, %1;" : "=r"(wi) : "f"(wv));
            sA[r][k] = ai;
            sW[r][k] = wi;
        }
        __syncthreads();
        #pragma unroll
        for (int k0 = 0; k0 < 64; k0 += 8) {
            uint32_t a0 = sA[warp * 16 + grp][k0 + tig];
            uint32_t a1 = sA[warp * 16 + grp + 8][k0 + tig];
            uint32_t a2 = sA[warp * 16 + grp][k0 + tig + 4];
            uint32_t a3 = sA[warp * 16 + grp + 8][k0 + tig + 4];
            #pragma unroll
            for (int nt = 0; nt < 8; nt++) {
                uint32_t b0 = sW[nt * 8 + grp][k0 + tig];
                uint32_t b1 = sW[nt * 8 + grp][k0 + tig + 4];
                asm volatile(
                    "mma.sync.aligned.m16n8k8.row.col.f32.tf32.tf32.f32 "
                    "{%0,%1,%2,%3}, {%4,%5,%6,%7}, {%8,%9}, {%0,%1,%2,%3};"
                    : "+f"(c[nt][0]), "+f"(c[nt][1]), "+f"(c[nt][2]), "+f"(c[nt][3])
                    : "r"(a0), "r"(a1), "r"(a2), "r"(a3), "r"(b0), "r"(b1));
            }
        }
        __syncthreads();
    }
    int r0 = rowBase + grp;
    int r1 = rowBase + grp + 8;
    float d0 = (r0 < NN) ? g_dinv[r0] : 0.f;
    float d1 = (r1 < NN) ? g_dinv[r1] : 0.f;
    #pragma unroll
    for (int nt = 0; nt < 8; nt++) {
        int colh = nt * 4 + tig;            // bf162 index (= col/2)
        if (r0 < NN)
            g_hwb[(long long)r0 * 32 + colh] = __floats2bfloat162_rn(c[nt][0] * d0, c[nt][1] * d0);
        if (r1 < NN)
            g_hwb[(long long)r1 * 32 + colh] = __floats2bfloat162_rn(c[nt][2] * d1, c[nt][3] * d1);
    }
}

__global__ __launch_bounds__(128) void k_gemm0_tc(const float* __restrict__ x) {
    gemm_tc_body<FIN>(x, g_M);
}
__global__ __launch_bounds__(128) void k_gemm12_tc(const float* __restrict__ W) {
    gemm_tc_body<D>(g_h, W);
}

// ---------------- CSR aggregation (bf16 gather) + self + bias + relu ----
// one warp per node; lane handles bf162 pair (2*lane, 2*lane+1).
// h[i] = relu( dinv[i] * (sum_src hws[src] + hws[i]) + b )   where hws = dinv*hw
__global__ __launch_bounds__(256) void k_aggregate(const float* __restrict__ bias) {
    int warp = (blockIdx.x * blockDim.x + threadIdx.x) >> 5;
    int lane = threadIdx.x & 31;
    if (warp >= NN) return;
    int i = warp;
    int s0 = g_rs[i];
    int deg = g_deg[i];
    float accx = 0.f, accy = 0.f;
    int e = s0, end = s0 + deg;
    for (; e + 4 <= end; e += 4) {
        int sa = g_csr[e], sb = g_csr[e + 1], sc = g_csr[e + 2], sd = g_csr[e + 3];
        __nv_bfloat162 va = g_hwb[(long long)sa * 32 + lane];
        __nv_bfloat162 vb = g_hwb[(long long)sb * 32 + lane];
        __nv_bfloat162 vc = g_hwb[(long long)sc * 32 + lane];
        __nv_bfloat162 vd = g_hwb[(long long)sd * 32 + lane];
        float2 fa = __bfloat1622float2(va);
        float2 fb = __bfloat1622float2(vb);
        float2 fc = __bfloat1622float2(vc);
        float2 fd = __bfloat1622float2(vd);
        accx += fa.x + fb.x + fc.x + fd.x;
        accy += fa.y + fb.y + fc.y + fd.y;
    }
    for (; e < end; e++) {
        int s = g_csr[e];
        float2 f = __bfloat1622float2(g_hwb[(long long)s * 32 + lane]);
        accx += f.x;
        accy += f.y;
    }
    float di = g_dinv[i];
    float2 hv = __bfloat1622float2(g_hwb[(long long)i * 32 + lane]);
    float2 bb = reinterpret_cast<const float2*>(bias)[lane];
    float vx = di * (accx + hv.x) + bb.x;
    float vy = di * (accy + hv.y) + bb.y;
    reinterpret_cast<float2*>(g_h)[(long long)i * 32 + lane] =
        make_float2(fmaxf(vx, 0.f), fmaxf(vy, 0.f));
}

// ---------------- tensor-core centroid distance + mean pooling ----------
// per block: 64 node rows x NPAD centroid cols via tf32 mma m16n8k8.
__global__ __launch_bounds__(128) void k_distpool_tc(const float* __restrict__ cent) {
    __shared__ uint32_t sH[64][68];
    __shared__ uint32_t sCt[NPAD][68];
    __shared__ float sh2[64];
    __shared__ float sc2[NPAD];
    __shared__ float sPool[NPAD];
    int t = threadIdx.x;
    int warp = t >> 5, lane = t & 31;
    int grp = lane >> 2, tig = lane & 3;
    int base = blockIdx.x * 64;

    for (int i = t; i < NPAD * 64; i += 128) {
        int col = i >> 6, k = i & 63;
        float v = (col < NCENT) ? cent[col * 64 + k] : 0.f;
        uint32_t b;
        asm("cvt.rna.tf32.f32 %0, %1;" : "=r"(b) : "f"(v));
        sCt[col][k] = b;
    }
    for (int i = t; i < 4096; i += 128) {
        int r = i >> 6, k = i & 63;
        int gn = base + r;
        float v = (gn < NN) ? g_h[(long long)gn * D + k] : 0.f;
        uint32_t b;
        asm("cvt.rna.tf32.f32 %0, %1;" : "=r"(b) : "f"(v));
        sH[r][k] = b;
    }
    if (t < NPAD) sPool[t] = 0.f;
    __syncthreads();

    // per-row |h|^2 (two threads per row)
    {
        int r = t >> 1, half = t & 1;
        float s = 0.f;
        #pragma unroll
        for (int k = 0; k < 32; k++) {
            float x = __uint_as_float(sH[r][half * 32 + k]);
            s += x * x;
        }
        s += __shfl_xor_sync(0xFFFFFFFFu, s, 1);
        if (half == 0) sh2[r] = s;
    }
    if (t < NPAD) {
        float s = 0.f;
        #pragma unroll
        for (int k = 0; k < D; k++) {
            float x = __uint_as_float(sCt[t][k]);
            s += x * x;
        }
        sc2[t] = s;
    }
    __syncthreads();

    float c[13][4];
    #pragma unroll
    for (int nt = 0; nt < 13; nt++)
        #pragma unroll
        for (int j = 0; j < 4; j++) c[nt][j] = 0.f;

    int rowS = warp * 16;
    #pragma unroll
    for (int k0 = 0; k0 < 64; k0 += 8) {
        uint32_t a0 = sH[rowS + grp][k0 + tig];
        uint32_t a1 = sH[rowS + grp + 8][k0 + tig];
        uint32_t a2 = sH[rowS + grp][k0 + tig + 4];
        uint32_t a3 = sH[rowS + grp + 8][k0 + tig + 4];
        #pragma unroll
        for (int nt = 0; nt < 13; nt++) {
            uint32_t b0 = sCt[nt * 8 + grp][k0 + tig];
            uint32_t b1 = sCt[nt * 8 + grp][k0 + tig + 4];
            asm volatile(
                "mma.sync.aligned.m16n8k8.row.col.f32.tf32.tf32.f32 "
                "{%0,%1,%2,%3}, {%4,%5,%6,%7}, {%8,%9}, {%0,%1,%2,%3};"
                : "+f"(c[nt][0]), "+f"(c[nt][1]), "+f"(c[nt][2]), "+f"(c[nt][3])
                : "r"(a0), "r"(a1), "r"(a2), "r"(a3), "r"(b0), "r"(b1));
        }
    }

    int lr0 = rowS + grp, lr1 = lr0 + 8;
    int gr0 = base + lr0, gr1 = base + lr1;
    float h20 = sh2[lr0], h21 = sh2[lr1];
    #pragma unroll
    for (int nt = 0; nt < 13; nt++) {
        int col0 = nt * 8 + tig * 2;
        int col1 = col0 + 1;
        float c20 = sc2[col0], c21 = sc2[col1];
        float d00 = fmaxf(h20 + c20 - 2.f * c[nt][0], 0.f) + EPSV;
        float d01 = fmaxf(h20 + c21 - 2.f * c[nt][1], 0.f) + EPSV;
        float d10 = fmaxf(h21 + c20 - 2.f * c[nt][2], 0.f) + EPSV;
        float d11 = fmaxf(h21 + c21 - 2.f * c[nt][3], 0.f) + EPSV;
        float q00, q01, q10, q11;
        asm("sqrt.approx.f32 %0, %1;" : "=f"(q00) : "f"(d00));
        asm("sqrt.approx.f32 %0, %1;" : "=f"(q01) : "f"(d01));
        asm("sqrt.approx.f32 %0, %1;" : "=f"(q10) : "f"(d10));
        asm("sqrt.approx.f32 %0, %1;" : "=f"(q11) : "f"(d11));
        float s0 = ((gr0 < NN) ? q00 : 0.f) + ((gr1 < NN) ? q10 : 0.f);
        float s1 = ((gr0 < NN) ? q01 : 0.f) + ((gr1 < NN) ? q11 : 0.f);
        #pragma unroll
        for (int m = 4; m < 32; m <<= 1) {
            s0 += __shfl_xor_sync(0xFFFFFFFFu, s0, m);
            s1 += __shfl_xor_sync(0xFFFFFFFFu, s1, m);
        }
        if (lane < 4) {
            if (col0 < NCENT) atomicAdd(&sPool[col0], s0);
            if (col1 < NCENT) atomicAdd(&sPool[col1], s1);
        }
    }
    __syncthreads();
    if (t < NCENT) atomicAdd(&g_pooled[t], sPool[t]);
}

// ---------------- final linear head ----------------
__global__ void k_out(const float* __restrict__ Wout, const float* __restrict__ bout,
                      float* __restrict__ out) {
    int c = threadIdx.x;
    if (c < NCLS) {
        const float invN = 1.0f / (float)NN;
        float s = 0.f;
        #pragma unroll
        for (int k = 0; k < NCENT; k++) s += (g_pooled[k] * invN) * Wout[c * NCENT + k];
        out[c] = s + bout[c];
    }
}

// ---------------- launch ----------------
extern "C" void kernel_launch(void* const* d_in, const int* in_sizes, int n_in,
                              void* d_out, int out_size) {
    const float* x    = (const float*)d_in[0];
    const int*   eiw  = (const int*)d_in[1];     // raw words; dtype detected on device
    const float* We   = (const float*)d_in[2];
    const float* Wg   = (const float*)d_in[3];   // [3,64,64]
    const float* bg   = (const float*)d_in[4];   // [3,64]
    const float* cent = (const float*)d_in[5];   // [100,64]
    const float* Wout = (const float*)d_in[6];   // [10,100]
    const float* bout = (const float*)d_in[7];   // [10]
    float*       out  = (float*)d_out;

    const int nScanBlk = (NN + 1023) / 1024;           // 98
    const int edgeBlk  = (NE + 255) / 256;             // 6250
    const int nodeBlk  = (NN + 255) / 256;             // 391
    const int gemmBlk  = (NN + 63) / 64;               // 1563
    const int aggBlk   = (NN * 32 + 255) / 256;        // 12500

    // init + CSR/norm build
    k_init<<<nodeBlk, 256>>>(eiw);
    k_degree<<<edgeBlk, 256>>>(eiw);
    k_scan1<<<nScanBlk, 1024>>>();
    k_scan2<<<1, 128>>>(nScanBlk);
    k_scan3<<<nScanBlk, 1024>>>();
    k_fill_csr<<<edgeBlk, 256>>>(eiw);

    // fused embed + layer0 weight:  M = W_gcn[0] @ W_embed
    k_computeM<<<(D * FIN + 255) / 256, 256>>>(Wg, We);

    // layer 0 (fused): hws = dinv * (x @ M^T)   (tf32 tensor cores, bf16 store)
    k_gemm0_tc<<<gemmBlk, 128>>>(x);
    k_aggregate<<<aggBlk, 256>>>(bg + 0 * D);

    // layer 1
    k_gemm12_tc<<<gemmBlk, 128>>>(Wg + 1 * D * D);
    k_aggregate<<<aggBlk, 256>>>(bg + 1 * D);

    // layer 2
    k_gemm12_tc<<<gemmBlk, 128>>>(Wg + 2 * D * D);
    k_aggregate<<<aggBlk, 256>>>(bg + 2 * D);

    // distance + pooling + head (tensor cores)
    k_distpool_tc<<<gemmBlk, 128>>>(cent);
    k_out<<<1, 32>>>(Wout, bout, out);
}